// round 2
// baseline (speedup 1.0000x reference)
#include <cuda_runtime.h>
#include <math.h>
#include <stdint.h>

#define Bn    16
#define Cin   128
#define Hh    32
#define Ww    32
#define HW    1024
#define MID   512
#define OUTC  111
#define NE    4
#define BOUT  (Bn*OUTC)   // 1776

// ---------------- scratch (device globals; no allocations allowed) ----------
__device__ float g_routing[Bn*NE];                        // [B][E]
__device__ float g_comb[(size_t)Bn*Cin*MID*49];           // [B][ic][o][49]  ~205MB
__device__ float g_y[(size_t)Bn*MID*HW];                  // raw conv output ~33.5MB
__device__ float g_ymean[Bn*MID];
__device__ float g_ca[Bn*MID];
__device__ float g_mf[Bn*HW];

// ---------------- init: zero count region + ymean ---------------------------
__global__ void init_kernel(float* out) {
    int i = blockIdx.x*256 + threadIdx.x;
    if (i < BOUT)    out[i] = 0.f;
    if (i < Bn*MID)  g_ymean[i] = 0.f;
}

// ---------------- routing: pooled mean -> softmax ---------------------------
__global__ void routing_kernel(const float* __restrict__ x,
                               const float* __restrict__ rw,
                               const float* __restrict__ rb) {
    int b = blockIdx.x;
    __shared__ float pooled[Cin];
    __shared__ float logit[NE];
    int t = threadIdx.x, warp = t >> 5, lane = t & 31;
    const float* xb = x + (size_t)b*Cin*HW;
    for (int c = warp; c < Cin; c += 8) {
        float s = 0.f;
        for (int i = lane; i < HW; i += 32) s += xb[c*HW + i];
        #pragma unroll
        for (int off = 16; off; off >>= 1) s += __shfl_down_sync(0xffffffffu, s, off);
        if (lane == 0) pooled[c] = s * (1.0f/HW);
    }
    __syncthreads();
    if (t < NE) {
        float s = rb[t];
        for (int c = 0; c < Cin; c++) s += pooled[c] * rw[t*Cin + c];
        logit[t] = s;
    }
    __syncthreads();
    if (t == 0) {
        float m = fmaxf(fmaxf(logit[0],logit[1]), fmaxf(logit[2],logit[3]));
        float e[NE]; float sum = 0.f;
        #pragma unroll
        for (int e_i = 0; e_i < NE; e_i++) { e[e_i] = expf(logit[e_i]-m); sum += e[e_i]; }
        float inv = 1.f/sum;
        #pragma unroll
        for (int e_i = 0; e_i < NE; e_i++) g_routing[b*NE + e_i] = e[e_i]*inv;
    }
}

// ---------------- combine experts into per-sample merged 7x7 bank ------------
// g_comb[b][ic][o][t7] = sum_e r[b,e]*(w7 + embed(w5) + embed(w3))
__global__ void combine_kernel(const float* __restrict__ w3,
                               const float* __restrict__ w5,
                               const float* __restrict__ w7) {
    __shared__ float r[Bn*NE];
    if (threadIdx.x < Bn*NE) r[threadIdx.x] = g_routing[threadIdx.x];
    __syncthreads();
    int idx = blockIdx.x*blockDim.x + threadIdx.x;
    const int TOT = MID*Cin*49;
    if (idx >= TOT) return;
    int o   = idx / (Cin*49);
    int rem = idx % (Cin*49);
    int ic  = rem / 49;
    int t   = rem % 49;
    int ty = t / 7, tx = t % 7;
    float v[NE];
    #pragma unroll
    for (int e = 0; e < NE; e++) {
        float w = w7[(((size_t)e*MID + o)*Cin + ic)*49 + t];
        if (ty >= 1 && ty <= 5 && tx >= 1 && tx <= 5)
            w += w5[(((size_t)e*MID + o)*Cin + ic)*25 + (ty-1)*5 + (tx-1)];
        if (ty >= 2 && ty <= 4 && tx >= 2 && tx <= 4)
            w += w3[(((size_t)e*MID + o)*Cin + ic)*9  + (ty-2)*3 + (tx-2)];
        v[e] = w;
    }
    #pragma unroll
    for (int b = 0; b < Bn; b++) {
        float s = r[b*NE+0]*v[0] + r[b*NE+1]*v[1] + r[b*NE+2]*v[2] + r[b*NE+3]*v[3];
        g_comb[(((size_t)b*Cin + ic)*MID + o)*49 + t] = s;
    }
}

// ---------------- main conv: per-sample 7x7, 512x(32x32), K=128 --------------
// grid (4 h-tiles, 8 o-tiles, 16 b); block 256.
// thread: col = t&31, og = t>>5; computes o = o0+og*8+k (k<8), rows h0+r (r<8), col.
__global__ void __launch_bounds__(256, 2)
conv_kernel(const float* __restrict__ x) {
    int b = blockIdx.z, ot = blockIdx.y, ht = blockIdx.x;
    int h0 = ht*8, o0 = ot*64;
    int tid = threadIdx.x;
    int col = tid & 31, og = tid >> 5;

    __shared__ float xs[8][14*38];     // 8 ic, 14 rows halo, 38 cols halo
    __shared__ float ws[2][64*49];     // [icl][o_local*49 + tap]

    float acc[8][8];
    #pragma unroll
    for (int k = 0; k < 8; k++)
        #pragma unroll
        for (int r = 0; r < 8; r++) acc[k][r] = 0.f;

    const float* xb = x + (size_t)b*Cin*HW;

    for (int ic0 = 0; ic0 < Cin; ic0 += 8) {
        __syncthreads();
        // stage input tile with halo (zero-padded)
        for (int i = tid; i < 8*532; i += 256) {
            int icl = i / 532, j = i % 532;
            int ri = j / 38, ci = j % 38;
            int hh = h0 - 3 + ri, wc = ci - 3;
            float v = 0.f;
            if ((unsigned)hh < 32u && (unsigned)wc < 32u)
                v = xb[(ic0+icl)*HW + hh*32 + wc];
            xs[icl][j] = v;
        }
        const float* combB = g_comb + (((size_t)b*Cin + ic0)*MID + o0)*49;
        for (int icp = 0; icp < 8; icp += 2) {
            __syncthreads();
            // stage weights for two input channels (coalesced global, conflict-free smem)
            for (int i = tid; i < 2*64*49; i += 256) {
                int l = i / 3136, j = i % 3136;   // j = ol*49 + t (matches global layout)
                ws[l][j] = combB[((size_t)(icp+l)*MID)*49 + j];
            }
            __syncthreads();
            #pragma unroll
            for (int l = 0; l < 2; l++) {
                const float* xsl = xs[icp + l];
                const float* wsl = ws[l] + og*8*49;
                #pragma unroll 1
                for (int ky = 0; ky < 7; ky++) {
                    #pragma unroll
                    for (int kx = 0; kx < 7; kx++) {
                        int t7 = ky*7 + kx;
                        float w[8];
                        #pragma unroll
                        for (int k = 0; k < 8; k++) w[k] = wsl[k*49 + t7];
                        float xv[8];
                        #pragma unroll
                        for (int r = 0; r < 8; r++)
                            xv[r] = xsl[(r+ky)*38 + col + kx];
                        #pragma unroll
                        for (int r = 0; r < 8; r++) {
                            #pragma unroll
                            for (int k = 0; k < 8; k++)
                                acc[k][r] += w[k] * xv[r];
                        }
                    }
                }
            }
        }
    }

    // write y + accumulate spatial means (for channel attention)
    #pragma unroll
    for (int k = 0; k < 8; k++) {
        int o = o0 + og*8 + k;
        float s = 0.f;
        float* yb = g_y + ((size_t)b*MID + o)*HW + h0*32 + col;
        #pragma unroll
        for (int r = 0; r < 8; r++) { yb[r*32] = acc[k][r]; s += acc[k][r]; }
        #pragma unroll
        for (int off = 16; off; off >>= 1) s += __shfl_down_sync(0xffffffffu, s, off);
        if (col == 0) atomicAdd(&g_ymean[b*MID + o], s);
    }
}

// ---------------- channel attention MLP -------------------------------------
__global__ void ca_kernel(const float* __restrict__ fc1w, const float* __restrict__ fc1b,
                          const float* __restrict__ fc2w, const float* __restrict__ fc2b) {
    int b = blockIdx.x, t = threadIdx.x;   // 512 threads
    __shared__ float m[MID];
    __shared__ float h[32];
    m[t] = g_ymean[b*MID + t] * (1.0f/HW);
    __syncthreads();
    if (t < 32) {
        float s = fc1b[t];
        for (int c = 0; c < MID; c++) s += fc1w[t*MID + c] * m[c];
        h[t] = fmaxf(s, 0.f);
    }
    __syncthreads();
    float s = fc2b[t];
    #pragma unroll
    for (int j = 0; j < 32; j++) s += fc2w[t*32 + j] * h[j];
    g_ca[b*MID + t] = 1.f/(1.f + expf(-s));
}

// ---------------- mask projection (1x1, 128 -> 1) ----------------------------
__global__ void mf_kernel(const float* __restrict__ mask,
                          const float* __restrict__ mpw,
                          const float* __restrict__ mpb) {
    __shared__ float w[Cin];
    int t = threadIdx.x;
    if (t < Cin) w[t] = mpw[t];
    __syncthreads();
    int b = blockIdx.y;
    int p = blockIdx.x*256 + t;
    const float* mb = mask + (size_t)b*Cin*HW + p;
    float s = mpb[0];
    #pragma unroll 8
    for (int c = 0; c < Cin; c++) s += mb[c*HW] * w[c];
    g_mf[b*HW + p] = s;
}

// ---------------- final: per-sample pred GEMM + sigmoid + count --------------
// grid (16 b, 8 p-tiles); block 128 (one spatial position each).
// ca folds into pred weights; mask_feat multiplies logits.
__global__ void __launch_bounds__(128)
final_kernel(const float* __restrict__ predw, float* __restrict__ out) {
    int b = blockIdx.x, pt = blockIdx.y;
    int t = threadIdx.x;
    int p = pt*128 + t;

    __shared__ float pw[64][112];
    float4 acc[28];
    #pragma unroll
    for (int j = 0; j < 28; j++) acc[j] = make_float4(0.f,0.f,0.f,0.f);

    for (int c0 = 0; c0 < MID; c0 += 64) {
        __syncthreads();
        for (int i = t; i < 64*112; i += 128) {
            int cl = i / 112, o = i % 112;
            float v = 0.f;
            if (o < OUTC) v = predw[o*MID + c0 + cl] * g_ca[b*MID + c0 + cl];
            pw[cl][o] = v;
        }
        __syncthreads();
        const float* yb = g_y + ((size_t)b*MID + c0)*HW + p;
        #pragma unroll 4
        for (int cl = 0; cl < 64; cl++) {
            float yv = yb[(size_t)cl*HW];
            const float4* pw4 = (const float4*)pw[cl];
            #pragma unroll
            for (int j = 0; j < 28; j++) {
                float4 w4 = pw4[j];
                acc[j].x += w4.x*yv; acc[j].y += w4.y*yv;
                acc[j].z += w4.z*yv; acc[j].w += w4.w*yv;
            }
        }
    }

    float mf = g_mf[b*HW + p];
    float* dbase = out + BOUT + ((size_t)b*OUTC)*HW + p;
    float* cnt   = out + b*OUTC;
    int lane = t & 31;

#define EMIT(OO, AV) do {                                              \
        if ((OO) < OUTC) {                                             \
            float dv = 1.f/(1.f + expf(-(AV)*mf));                     \
            dbase[(size_t)(OO)*HW] = dv;                               \
            float s_ = dv;                                             \
            s_ += __shfl_down_sync(0xffffffffu, s_, 16);               \
            s_ += __shfl_down_sync(0xffffffffu, s_, 8);                \
            s_ += __shfl_down_sync(0xffffffffu, s_, 4);                \
            s_ += __shfl_down_sync(0xffffffffu, s_, 2);                \
            s_ += __shfl_down_sync(0xffffffffu, s_, 1);                \
            if (lane == 0) atomicAdd(&cnt[(OO)], s_);                  \
        }                                                              \
    } while (0)

    #pragma unroll
    for (int j = 0; j < 28; j++) {
        float4 a = acc[j];
        EMIT(4*j+0, a.x); EMIT(4*j+1, a.y);
        EMIT(4*j+2, a.z); EMIT(4*j+3, a.w);
    }
#undef EMIT
}

// ---------------- launch ------------------------------------------------------
extern "C" void kernel_launch(void* const* d_in, const int* in_sizes, int n_in,
                              void* d_out, int out_size) {
    const float* x        = (const float*)d_in[0];
    const float* mask     = (const float*)d_in[1];
    const float* w3       = (const float*)d_in[2];
    const float* w5       = (const float*)d_in[3];
    const float* w7       = (const float*)d_in[4];
    const float* router_w = (const float*)d_in[5];
    const float* router_b = (const float*)d_in[6];
    const float* fc1_w    = (const float*)d_in[7];
    const float* fc1_b    = (const float*)d_in[8];
    const float* fc2_w    = (const float*)d_in[9];
    const float* fc2_b    = (const float*)d_in[10];
    const float* mpw      = (const float*)d_in[11];
    const float* mpb      = (const float*)d_in[12];
    const float* pred_w   = (const float*)d_in[13];
    float* out = (float*)d_out;

    init_kernel<<<32, 256>>>(out);
    routing_kernel<<<Bn, 256>>>(x, router_w, router_b);
    {
        const int TOT = MID*Cin*49;
        combine_kernel<<<(TOT + 255)/256, 256>>>(w3, w5, w7);
    }
    conv_kernel<<<dim3(4, 8, Bn), 256>>>(x);
    mf_kernel<<<dim3(4, Bn), 256>>>(mask, mpw, mpb);
    ca_kernel<<<Bn, 512>>>(fc1_w, fc1_b, fc2_w, fc2_b);
    final_kernel<<<dim3(Bn, 8), 128>>>(pred_w, out);
}

// round 8
// speedup vs baseline: 1.5387x; 1.5387x over previous
#include <cuda_runtime.h>
#include <cuda.h>
#include <math.h>
#include <stdint.h>

#define Bn    16
#define Cin   128
#define HW    1024
#define MID   512
#define OUTC  111
#define NE    4
#define BOUT  (Bn*OUTC)
#define NTOT  (49*MID*Cin)

__device__ __align__(1024) float g_routing[Bn*NE];
__device__ __align__(1024) float g_wm[(size_t)NE*NTOT];
__device__ __align__(1024) float g_afh[(size_t)Bn*NTOT];
__device__ __align__(1024) float g_afl[(size_t)Bn*NTOT];
__device__ __align__(1024) float g_xph[(size_t)Bn*38*Cin*40];
__device__ __align__(1024) float g_xpl[(size_t)Bn*38*Cin*40];
__device__ __align__(1024) float g_y[(size_t)Bn*MID*HW];
__device__ float g_ymean[Bn*MID];
__device__ float g_mf[Bn*HW];
__device__ float g_ca[Bn*MID];

__device__ __forceinline__ uint32_t smem_u32(const void* p){
    uint32_t a; asm("{ .reg .u64 t; cvta.to.shared.u64 t, %1; cvt.u32.u64 %0, t; }"
                    : "=r"(a) : "l"(p)); return a;
}
__device__ __forceinline__ float ftf32(float f){
    uint32_t u; asm("cvt.rna.tf32.f32 %0, %1;" : "=r"(u) : "f"(f));
    return __uint_as_float(u);
}
__device__ __forceinline__ void cp16(uint32_t dst, const void* src){
    asm volatile("cp.async.cg.shared.global [%0], [%1], 16;" :: "r"(dst), "l"(src));
}
__device__ __forceinline__ void cpcommit(){
    asm volatile("cp.async.commit_group;" ::: "memory");
}
template<int N> __device__ __forceinline__ void cpwait(){
    asm volatile("cp.async.wait_group %0;" :: "n"(N) : "memory");
}
#define LDS128(r0,r1,r2,r3,addr) \
    asm volatile("ld.shared.v4.b32 {%0,%1,%2,%3}, [%4];" \
        : "=r"(r0),"=r"(r1),"=r"(r2),"=r"(r3) : "r"(addr))
#define LDS32(r0,addr) \
    asm volatile("ld.shared.b32 %0, [%1];" : "=r"(r0) : "r"(addr))
#define MMA_TF32(d, a, bfr) \
    asm volatile("mma.sync.aligned.m16n8k8.row.col.f32.tf32.tf32.f32 " \
        "{%0,%1,%2,%3}, {%4,%5,%6,%7}, {%8,%9}, {%0,%1,%2,%3};" \
        : "+f"((d)[0]),"+f"((d)[1]),"+f"((d)[2]),"+f"((d)[3]) \
        : "r"((a)[0]),"r"((a)[1]),"r"((a)[2]),"r"((a)[3]), \
          "r"((bfr)[0]),"r"((bfr)[1]))

__global__ void init_kernel(float* out) {
    int i = blockIdx.x*256 + threadIdx.x;
    if (i < BOUT)   out[i] = 0.f;
    if (i < Bn*MID) g_ymean[i] = 0.f;
}

__global__ void xp_zero() {
    size_t i = (size_t)blockIdx.x*256 + threadIdx.x;
    if (i < (size_t)Bn*38*Cin*40) { g_xph[i] = 0.f; g_xpl[i] = 0.f; }
}

__global__ void xp_fill(const float* __restrict__ x) {
    int b = blockIdx.y, h = blockIdx.x;
    int tid = threadIdx.x;
    int w = tid & 31, icg = tid >> 5;
    #pragma unroll 4
    for (int i = 0; i < 32; i++) {
        int ic = icg*32 + i;
        float v = x[((size_t)b*Cin + ic)*HW + h*32 + w];
        float hi = ftf32(v);
        size_t d = (((size_t)b*38 + h + 3)*Cin + ic)*40 + w + 3;
        g_xph[d] = hi;
        g_xpl[d] = ftf32(v - hi);
    }
}

__global__ void routing_kernel(const float* __restrict__ x,
                               const float* __restrict__ rw,
                               const float* __restrict__ rb) {
    int b = blockIdx.x;
    __shared__ float pooled[Cin];
    __shared__ float logit[NE];
    int t = threadIdx.x, warp = t >> 5, lane = t & 31;
    const float* xb = x + (size_t)b*Cin*HW;
    for (int c = warp; c < Cin; c += 8) {
        float s = 0.f;
        for (int i = lane; i < HW; i += 32) s += xb[c*HW + i];
        #pragma unroll
        for (int off = 16; off; off >>= 1) s += __shfl_down_sync(0xffffffffu, s, off);
        if (lane == 0) pooled[c] = s * (1.0f/HW);
    }
    __syncthreads();
    if (t < NE) {
        float s = rb[t];
        for (int c = 0; c < Cin; c++) s += pooled[c] * rw[t*Cin + c];
        logit[t] = s;
    }
    __syncthreads();
    if (t == 0) {
        float m = fmaxf(fmaxf(logit[0],logit[1]), fmaxf(logit[2],logit[3]));
        float e[NE]; float sum = 0.f;
        #pragma unroll
        for (int i = 0; i < NE; i++) { e[i] = expf(logit[i]-m); sum += e[i]; }
        float inv = 1.f/sum;
        #pragma unroll
        for (int i = 0; i < NE; i++) g_routing[b*NE + i] = e[i]*inv;
    }
}

__global__ void merge_kernel(const float* __restrict__ w3,
                             const float* __restrict__ w5,
                             const float* __restrict__ w7) {
    int o = blockIdx.x, e = blockIdx.y;
    __shared__ float s7[Cin*49];
    __shared__ float s5[Cin*25];
    __shared__ float s3[Cin*9];
    size_t base = ((size_t)e*MID + o)*Cin;
    int t = threadIdx.x;
    for (int i = t; i < Cin*49; i += 256) s7[i] = w7[base*49 + i];
    for (int i = t; i < Cin*25; i += 256) s5[i] = w5[base*25 + i];
    for (int i = t; i < Cin*9;  i += 256) s3[i] = w3[base*9  + i];
    __syncthreads();
    for (int i = t; i < 49*Cin; i += 256) {
        int tap = i >> 7, ic = i & 127;
        int ty = tap / 7, tx = tap % 7;
        float v = s7[ic*49 + tap];
        if ((unsigned)(ty-1) < 5u && (unsigned)(tx-1) < 5u) v += s5[ic*25 + (ty-1)*5 + (tx-1)];
        if ((unsigned)(ty-2) < 3u && (unsigned)(tx-2) < 3u) v += s3[ic*9  + (ty-2)*3 + (tx-2)];
        g_wm[(((size_t)e*49 + tap)*MID + o)*Cin + ic] = v;
    }
}

// A-frag register order (PTX m16n8k8.tf32, ROW-FAST):
//   a0=(o, ic), a1=(o+8, ic), a2=(o, ic+1), a3=(o+8, ic+1)
#define FM_SMEM (4*128*33*4)
__global__ void __launch_bounds__(256)
fragmix_kernel() {
    extern __shared__ float ws[];
    __shared__ float r[Bn*NE];
    int t = blockIdx.x;
    int icq = blockIdx.y & 3, mtb = blockIdx.y >> 2;
    int tid = threadIdx.x;
    if (tid < Bn*NE) r[tid] = g_routing[tid];
    for (int idx = tid; idx < 4*128*32; idx += 256) {
        int e = idx >> 12, ol = (idx >> 5) & 127, icl = idx & 31;
        ws[(e*128 + ol)*33 + icl] =
            g_wm[(((size_t)e*49 + t)*MID + mtb*128 + ol)*Cin + icq*32 + icl];
    }
    __syncthreads();
    #pragma unroll
    for (int j = 0; j < 4; j++) {
        int pos = tid + j*256;
        int kk = pos >> 8, mt = (pos >> 5) & 7, ln = pos & 31;
        int cc = ln & 3, rr = ln >> 2;
        int o  = mt*16 + rr;
        int ic = kk*8 + 2*cc;
        float e00[4], e01[4], e10[4], e11[4];
        #pragma unroll
        for (int e = 0; e < 4; e++) {
            int base = (e*128 + o)*33 + ic;
            e00[e] = ws[base];          e01[e] = ws[base + 1];
            e10[e] = ws[base + 8*33];   e11[e] = ws[base + 8*33 + 1];
        }
        size_t cb = (((size_t)t*4 + icq)*4 + mtb)*4096 + (size_t)pos*4;
        #pragma unroll
        for (int b = 0; b < Bn; b++) {
            float r0 = r[b*4], r1 = r[b*4+1], r2 = r[b*4+2], r3 = r[b*4+3];
            float wA = r0*e00[0] + r1*e00[1] + r2*e00[2] + r3*e00[3]; // W[o][ic]
            float wB = r0*e10[0] + r1*e10[1] + r2*e10[2] + r3*e10[3]; // W[o+8][ic]
            float wC = r0*e01[0] + r1*e01[1] + r2*e01[2] + r3*e01[3]; // W[o][ic+1]
            float wD = r0*e11[0] + r1*e11[1] + r2*e11[2] + r3*e11[3]; // W[o+8][ic+1]
            float4 vh, vl;
            vh.x = ftf32(wA); vl.x = ftf32(wA - vh.x);
            vh.y = ftf32(wB); vl.y = ftf32(wB - vh.y);
            vh.z = ftf32(wC); vl.z = ftf32(wC - vh.z);
            vh.w = ftf32(wD); vl.w = ftf32(wD - vh.w);
            *(float4*)&g_afh[(size_t)b*NTOT + cb] = vh;
            *(float4*)&g_afl[(size_t)b*NTOT + cb] = vl;
        }
    }
}

#define A_HALF    16384
#define A_BYTES2  32768
#define B_PITCH   324
#define B_HALF    (32*B_PITCH*4)
#define B_BYTES2  (2*B_HALF)
#define A_ALL     (2*A_BYTES2)
#define SMEM_CONV (A_ALL + 2*B_BYTES2)

__global__ void __launch_bounds__(256)
conv_mma() {
    extern __shared__ __align__(16) char smem[];
    uint32_t sb = smem_u32(smem);
    int tid = threadIdx.x, wid = tid >> 5, lane = tid & 31;
    int c = lane & 3, rl = lane >> 2;
    int wm = wid & 1, wn = wid >> 1;
    int mtb = blockIdx.x, nt = blockIdx.y, b = blockIdx.z;

    const float* Abh = g_afh + (size_t)b*NTOT;
    const float* Abl = g_afl + (size_t)b*NTOT;

    float acc[4][8][4];
    #pragma unroll
    for (int mi = 0; mi < 4; mi++)
        #pragma unroll
        for (int ni = 0; ni < 8; ni++)
            #pragma unroll
            for (int q = 0; q < 4; q++) acc[mi][ni][q] = 0.f;

    uint32_t bb[8];
    #pragma unroll
    for (int ni = 0; ni < 8; ni++) {
        int p = wn*64 + ni*8 + rl;
        bb[ni] = (uint32_t)(((p >> 5)*40 + (p & 31)) << 2);
    }

    auto issueA = [&](int m, int buf) {
        int j = m/7, dx = m - j*7;
        int t = (j >> 2)*7 + dx, icq = j & 3;
        size_t off = ((size_t)((t*4 + icq)*4 + mtb))*4096 + tid*4;
        uint32_t dst = sb + buf*A_BYTES2 + tid*16;
        #pragma unroll
        for (int q = 0; q < 4; q++) cp16(dst + q*4096, Abh + off + q*1024);
        #pragma unroll
        for (int q = 0; q < 4; q++) cp16(dst + A_HALF + q*4096, Abl + off + q*1024);
    };
    auto issueB = [&](int j, int buf) {
        int dy = j >> 2, icq = j & 3;
        int k = tid >> 3, h = tid & 7;
        size_t off = ((size_t)(b*38 + nt*8 + h + dy)*Cin + icq*32 + k)*40;
        uint32_t dst = sb + A_ALL + buf*B_BYTES2 + (uint32_t)((k*B_PITCH + h*40) << 2);
        #pragma unroll
        for (int q = 0; q < 10; q++) cp16(dst + q*16, g_xph + off + q*4);
        #pragma unroll
        for (int q = 0; q < 10; q++) cp16(dst + B_HALF + q*16, g_xpl + off + q*4);
    };

    issueB(0, 0); cpcommit();
    issueA(0, 0); cpcommit();
    bool pb = false;

    int j = 0, dx = 0;
    for (int m = 0; m < 196; m++) {
        if (m == 0)      cpwait<0>();
        else if (pb)     cpwait<1>();
        else             cpwait<0>();
        __syncthreads();
        if (m + 1 < 196) { issueA(m + 1, (m + 1) & 1); cpcommit(); }
        pb = false;
        if (dx == 0 && j < 27) { issueB(j + 1, (j + 1) & 1); cpcommit(); pb = true; }

        uint32_t aSh = sb + (m & 1)*A_BYTES2;
        uint32_t aSl = aSh + A_HALF;
        uint32_t bSh = sb + A_ALL + (j & 1)*B_BYTES2 + (uint32_t)(dx << 2);
        uint32_t bSl = bSh + B_HALF;
        #pragma unroll
        for (int ks = 0; ks < 4; ks++) {
            uint32_t bfh[8][2], bfl[8][2];
            uint32_t krow = (uint32_t)(((ks*8 + 2*c)*B_PITCH) << 2);
            uint32_t krow2 = krow + (B_PITCH << 2);
            #pragma unroll
            for (int ni = 0; ni < 8; ni++) {
                LDS32(bfh[ni][0], bSh + krow  + bb[ni]);
                LDS32(bfh[ni][1], bSh + krow2 + bb[ni]);
                LDS32(bfl[ni][0], bSl + krow  + bb[ni]);
                LDS32(bfl[ni][1], bSl + krow2 + bb[ni]);
            }
            uint32_t af[4][4];
            uint32_t aoff = (uint32_t)((((ks*8 + wm*4)*32) + lane) << 4);
            #pragma unroll
            for (int mi = 0; mi < 4; mi++)
                LDS128(af[mi][0], af[mi][1], af[mi][2], af[mi][3],
                       aSh + aoff + (uint32_t)(mi*512));
            #pragma unroll
            for (int mi = 0; mi < 4; mi++)
                #pragma unroll
                for (int ni = 0; ni < 8; ni++)
                    MMA_TF32(acc[mi][ni], af[mi], bfh[ni]);
            #pragma unroll
            for (int mi = 0; mi < 4; mi++)
                #pragma unroll
                for (int ni = 0; ni < 8; ni++)
                    MMA_TF32(acc[mi][ni], af[mi], bfl[ni]);
            #pragma unroll
            for (int mi = 0; mi < 4; mi++)
                LDS128(af[mi][0], af[mi][1], af[mi][2], af[mi][3],
                       aSl + aoff + (uint32_t)(mi*512));
            #pragma unroll
            for (int mi = 0; mi < 4; mi++)
                #pragma unroll
                for (int ni = 0; ni < 8; ni++)
                    MMA_TF32(acc[mi][ni], af[mi], bfh[ni]);
        }
        if (++dx == 7) { dx = 0; j++; }
    }

    int o0 = mtb*128 + wm*64;
    int p0 = nt*256 + wn*64;
    #pragma unroll
    for (int mi = 0; mi < 4; mi++) {
        int o = o0 + mi*16 + rl;
        float s0 = 0.f, s1 = 0.f;
        float* y0 = g_y + ((size_t)b*MID + o)*HW;
        float* y1 = g_y + ((size_t)b*MID + o + 8)*HW;
        #pragma unroll
        for (int ni = 0; ni < 8; ni++) {
            int p = p0 + ni*8 + 2*c;
            float2 v0 = make_float2(acc[mi][ni][0], acc[mi][ni][1]);
            float2 v1 = make_float2(acc[mi][ni][2], acc[mi][ni][3]);
            *(float2*)(y0 + p) = v0;
            *(float2*)(y1 + p) = v1;
            s0 += v0.x + v0.y;
            s1 += v1.x + v1.y;
        }
        s0 += __shfl_xor_sync(0xffffffffu, s0, 1);
        s0 += __shfl_xor_sync(0xffffffffu, s0, 2);
        s1 += __shfl_xor_sync(0xffffffffu, s1, 1);
        s1 += __shfl_xor_sync(0xffffffffu, s1, 2);
        if (c == 0) {
            atomicAdd(&g_ymean[b*MID + o], s0);
            atomicAdd(&g_ymean[b*MID + o + 8], s1);
        }
    }
}

__global__ void ca_kernel(const float* __restrict__ fc1w, const float* __restrict__ fc1b,
                          const float* __restrict__ fc2w, const float* __restrict__ fc2b) {
    int b = blockIdx.x, t = threadIdx.x;
    __shared__ float m[MID];
    __shared__ float h[32];
    m[t] = g_ymean[b*MID + t] * (1.0f/HW);
    __syncthreads();
    if (t < 32) {
        float s = fc1b[t];
        for (int c = 0; c < MID; c++) s += fc1w[t*MID + c] * m[c];
        h[t] = fmaxf(s, 0.f);
    }
    __syncthreads();
    float s = fc2b[t];
    #pragma unroll
    for (int j = 0; j < 32; j++) s += fc2w[t*32 + j] * h[j];
    g_ca[b*MID + t] = 1.f/(1.f + expf(-s));
}

__global__ void mf_kernel(const float* __restrict__ mask,
                          const float* __restrict__ mpw,
                          const float* __restrict__ mpb) {
    __shared__ float w[Cin];
    int t = threadIdx.x;
    if (t < Cin) w[t] = mpw[t];
    __syncthreads();
    int b = blockIdx.y;
    int p = blockIdx.x*256 + t;
    const float* mb = mask + (size_t)b*Cin*HW + p;
    float s = mpb[0];
    #pragma unroll 8
    for (int c = 0; c < Cin; c++) s += mb[c*HW] * w[c];
    g_mf[b*HW + p] = s;
}

__global__ void __launch_bounds__(128)
final_kernel(const float* __restrict__ predw, float* __restrict__ out) {
    int b = blockIdx.x, pt = blockIdx.y;
    int t = threadIdx.x;
    int p = pt*128 + t;

    __shared__ float pw[64][112];
    float4 acc[28];
    #pragma unroll
    for (int j = 0; j < 28; j++) acc[j] = make_float4(0.f,0.f,0.f,0.f);

    for (int c0 = 0; c0 < MID; c0 += 64) {
        __syncthreads();
        for (int i = t; i < 64*112; i += 128) {
            int cl = i / 112, o = i % 112;
            float v = 0.f;
            if (o < OUTC) v = predw[o*MID + c0 + cl] * g_ca[b*MID + c0 + cl];
            pw[cl][o] = v;
        }
        __syncthreads();
        const float* yb = g_y + ((size_t)b*MID + c0)*HW + p;
        #pragma unroll 4
        for (int cl = 0; cl < 64; cl++) {
            float yv = yb[(size_t)cl*HW];
            const float4* pw4 = (const float4*)pw[cl];
            #pragma unroll
            for (int j = 0; j < 28; j++) {
                float4 w4 = pw4[j];
                acc[j].x += w4.x*yv; acc[j].y += w4.y*yv;
                acc[j].z += w4.z*yv; acc[j].w += w4.w*yv;
            }
        }
    }

    float mf = g_mf[b*HW + p];
    float* dbase = out + BOUT + ((size_t)b*OUTC)*HW + p;
    float* cnt   = out + b*OUTC;
    int lane = t & 31;

#define EMIT(OO, AV) do {                                              \
        if ((OO) < OUTC) {                                             \
            float dv = 1.f/(1.f + expf(-(AV)*mf));                     \
            dbase[(size_t)(OO)*HW] = dv;                               \
            float s_ = dv;                                             \
            s_ += __shfl_down_sync(0xffffffffu, s_, 16);               \
            s_ += __shfl_down_sync(0xffffffffu, s_, 8);                \
            s_ += __shfl_down_sync(0xffffffffu, s_, 4);                \
            s_ += __shfl_down_sync(0xffffffffu, s_, 2);                \
            s_ += __shfl_down_sync(0xffffffffu, s_, 1);                \
            if (lane == 0) atomicAdd(&cnt[(OO)], s_);                  \
        }                                                              \
    } while (0)

    #pragma unroll
    for (int j = 0; j < 28; j++) {
        float4 a = acc[j];
        EMIT(4*j+0, a.x); EMIT(4*j+1, a.y);
        EMIT(4*j+2, a.z); EMIT(4*j+3, a.w);
    }
#undef EMIT
}

extern "C" void kernel_launch(void* const* d_in, const int* in_sizes, int n_in,
                              void* d_out, int out_size) {
    const float* x        = (const float*)d_in[0];
    const float* mask     = (const float*)d_in[1];
    const float* w3       = (const float*)d_in[2];
    const float* w5       = (const float*)d_in[3];
    const float* w7       = (const float*)d_in[4];
    const float* router_w = (const float*)d_in[5];
    const float* router_b = (const float*)d_in[6];
    const float* fc1_w    = (const float*)d_in[7];
    const float* fc1_b    = (const float*)d_in[8];
    const float* fc2_w    = (const float*)d_in[9];
    const float* fc2_b    = (const float*)d_in[10];
    const float* mpw      = (const float*)d_in[11];
    const float* mpb      = (const float*)d_in[12];
    const float* pred_w   = (const float*)d_in[13];
    float* out = (float*)d_out;

    init_kernel<<<32, 256>>>(out);
    routing_kernel<<<Bn, 256>>>(x, router_w, router_b);
    {
        size_t n = (size_t)Bn*38*Cin*40;
        xp_zero<<<(int)((n + 255)/256), 256>>>();
    }
    xp_fill<<<dim3(32, Bn), 128>>>(x);
    merge_kernel<<<dim3(MID, NE), 256>>>(w3, w5, w7);

    cudaFuncSetAttribute(fragmix_kernel, cudaFuncAttributeMaxDynamicSharedMemorySize, FM_SMEM);
    fragmix_kernel<<<dim3(49, 16), 256, FM_SMEM>>>();

    cudaFuncSetAttribute(conv_mma, cudaFuncAttributeMaxDynamicSharedMemorySize, SMEM_CONV);
    conv_mma<<<dim3(4, 4, Bn), 256, SMEM_CONV>>>();

    mf_kernel<<<dim3(4, Bn), 256>>>(mask, mpw, mpb);
    ca_kernel<<<Bn, 512>>>(fc1_w, fc1_b, fc2_w, fc2_b);
    final_kernel<<<dim3(Bn, 8), 128>>>(pred_w, out);
}

// round 9
// speedup vs baseline: 2.4959x; 1.6221x over previous
#include <cuda_runtime.h>
#include <cuda.h>
#include <cuda_bf16.h>
#include <math.h>
#include <stdint.h>

#define Bn    16
#define Cin   128
#define HW    1024
#define MID   512
#define OUTC  111
#define NE    4
#define BOUT  (Bn*OUTC)
#define NTOT  (49*MID*Cin)
#define NAPK  (49*4*4*2048)     // packed A words per sample (uint32)
#define XPW   (38*64*40)        // packed input words per sample

__device__ __align__(1024) float    g_routing[Bn*NE];
__device__ __align__(1024) float    g_wm[(size_t)NE*NTOT];        // [e][t][o][ic]
__device__ __align__(1024) uint32_t g_afh[(size_t)Bn*NAPK];       // frag-major A hi (bf16x2)
__device__ __align__(1024) uint32_t g_afl[(size_t)Bn*NAPK];       // lo
__device__ __align__(1024) uint32_t g_xph[(size_t)Bn*XPW];        // [b][ph][icp64][w40] hi
__device__ __align__(1024) uint32_t g_xpl[(size_t)Bn*XPW];        // lo
__device__ __align__(1024) float    g_y[(size_t)Bn*MID*HW];
__device__ float g_ymean[Bn*MID];
__device__ float g_mf[Bn*HW];
__device__ float g_ca[Bn*MID];

__device__ __forceinline__ uint32_t smem_u32(const void* p){
    uint32_t a; asm("{ .reg .u64 t; cvta.to.shared.u64 t, %1; cvt.u32.u64 %0, t; }"
                    : "=r"(a) : "l"(p)); return a;
}
__device__ __forceinline__ uint32_t pk2(float a, float b){
    __nv_bfloat162 t = __floats2bfloat162_rn(a, b);   // a -> low 16 bits
    return *reinterpret_cast<uint32_t*>(&t);
}
__device__ __forceinline__ float bfr(float w){
    return __bfloat162float(__float2bfloat16_rn(w));
}
__device__ __forceinline__ void cp16(uint32_t dst, const void* src){
    asm volatile("cp.async.cg.shared.global [%0], [%1], 16;" :: "r"(dst), "l"(src));
}
__device__ __forceinline__ void cpcommit(){
    asm volatile("cp.async.commit_group;" ::: "memory");
}
template<int N> __device__ __forceinline__ void cpwait(){
    asm volatile("cp.async.wait_group %0;" :: "n"(N) : "memory");
}
#define LDS128(r0,r1,r2,r3,addr) \
    asm volatile("ld.shared.v4.b32 {%0,%1,%2,%3}, [%4];" \
        : "=r"(r0),"=r"(r1),"=r"(r2),"=r"(r3) : "r"(addr))
#define LDS32(r0,addr) \
    asm volatile("ld.shared.b32 %0, [%1];" : "=r"(r0) : "r"(addr))
#define MMA_BF16(d, a, bfrg) \
    asm volatile("mma.sync.aligned.m16n8k16.row.col.f32.bf16.bf16.f32 " \
        "{%0,%1,%2,%3}, {%4,%5,%6,%7}, {%8,%9}, {%0,%1,%2,%3};" \
        : "+f"((d)[0]),"+f"((d)[1]),"+f"((d)[2]),"+f"((d)[3]) \
        : "r"((a)[0]),"r"((a)[1]),"r"((a)[2]),"r"((a)[3]), \
          "r"((bfrg)[0]),"r"((bfrg)[1]))

__global__ void init_kernel(float* out) {
    int i = blockIdx.x*256 + threadIdx.x;
    if (i < BOUT)   out[i] = 0.f;
    if (i < Bn*MID) g_ymean[i] = 0.f;
}

__global__ void xp_zero() {
    size_t i = (size_t)blockIdx.x*256 + threadIdx.x;
    if (i < (size_t)Bn*XPW) { g_xph[i] = 0u; g_xpl[i] = 0u; }
}

// x[b][ic][h][w] -> packed bf16 pairs [b][h+3][icp][w+3]
__global__ void xp_fill(const float* __restrict__ x) {
    int b = blockIdx.y, h = blockIdx.x;
    int tid = threadIdx.x;
    int w = tid & 31, g = tid >> 5;        // g in 0..3
    for (int i = 0; i < 16; i++) {
        int icp = g*16 + i;
        float f0 = x[((size_t)b*Cin + 2*icp    )*HW + h*32 + w];
        float f1 = x[((size_t)b*Cin + 2*icp + 1)*HW + h*32 + w];
        float h0 = bfr(f0), h1 = bfr(f1);
        size_t d = (((size_t)b*38 + h + 3)*64 + icp)*40 + w + 3;
        g_xph[d] = pk2(h0, h1);
        g_xpl[d] = pk2(f0 - h0, f1 - h1);
    }
}

__global__ void routing_kernel(const float* __restrict__ x,
                               const float* __restrict__ rw,
                               const float* __restrict__ rb) {
    int b = blockIdx.x;
    __shared__ float pooled[Cin];
    __shared__ float logit[NE];
    int t = threadIdx.x, warp = t >> 5, lane = t & 31;
    const float* xb = x + (size_t)b*Cin*HW;
    for (int c = warp; c < Cin; c += 8) {
        float s = 0.f;
        for (int i = lane; i < HW; i += 32) s += xb[c*HW + i];
        #pragma unroll
        for (int off = 16; off; off >>= 1) s += __shfl_down_sync(0xffffffffu, s, off);
        if (lane == 0) pooled[c] = s * (1.0f/HW);
    }
    __syncthreads();
    if (t < NE) {
        float s = rb[t];
        for (int c = 0; c < Cin; c++) s += pooled[c] * rw[t*Cin + c];
        logit[t] = s;
    }
    __syncthreads();
    if (t == 0) {
        float m = fmaxf(fmaxf(logit[0],logit[1]), fmaxf(logit[2],logit[3]));
        float e[NE]; float sum = 0.f;
        #pragma unroll
        for (int i = 0; i < NE; i++) { e[i] = expf(logit[i]-m); sum += e[i]; }
        float inv = 1.f/sum;
        #pragma unroll
        for (int i = 0; i < NE; i++) g_routing[b*NE + i] = e[i]*inv;
    }
}

__global__ void merge_kernel(const float* __restrict__ w3,
                             const float* __restrict__ w5,
                             const float* __restrict__ w7) {
    int o = blockIdx.x, e = blockIdx.y;
    __shared__ float s7[Cin*49];
    __shared__ float s5[Cin*25];
    __shared__ float s3[Cin*9];
    size_t base = ((size_t)e*MID + o)*Cin;
    int t = threadIdx.x;
    for (int i = t; i < Cin*49; i += 256) s7[i] = w7[base*49 + i];
    for (int i = t; i < Cin*25; i += 256) s5[i] = w5[base*25 + i];
    for (int i = t; i < Cin*9;  i += 256) s3[i] = w3[base*9  + i];
    __syncthreads();
    for (int i = t; i < 49*Cin; i += 256) {
        int tap = i >> 7, ic = i & 127;
        int ty = tap / 7, tx = tap % 7;
        float v = s7[ic*49 + tap];
        if ((unsigned)(ty-1) < 5u && (unsigned)(tx-1) < 5u) v += s5[ic*25 + (ty-1)*5 + (tx-1)];
        if ((unsigned)(ty-2) < 3u && (unsigned)(tx-2) < 3u) v += s3[ic*9  + (ty-2)*3 + (tx-2)];
        g_wm[(((size_t)e*49 + tap)*MID + o)*Cin + ic] = v;
    }
}

// A-frag m16n8k16 bf16 (ROW-FAST, packed pairs):
//   a0 = pack(W[o][k0],W[o][k1])  a1 = pack(W[o+8][k0],W[o+8][k1])
//   a2 = pack(W[o][k8],W[o][k9])  a3 = pack(W[o+8][k8],W[o+8][k9])
// chunk = ((t*4+icq)*4+mtb), 2048 words: idx = (ks*8+mt)*32 + lane, 4 words each.
#define FM_SMEM (4*128*33*4)
__global__ void __launch_bounds__(256)
fragmix_kernel() {
    extern __shared__ float ws[];
    __shared__ float r[Bn*NE];
    int t = blockIdx.x;
    int icq = blockIdx.y & 3, mtb = blockIdx.y >> 2;
    int tid = threadIdx.x;
    if (tid < Bn*NE) r[tid] = g_routing[tid];
    for (int idx = tid; idx < 4*128*32; idx += 256) {
        int e = idx >> 12, ol = (idx >> 5) & 127, icl = idx & 31;
        ws[(e*128 + ol)*33 + icl] =
            g_wm[(((size_t)e*49 + t)*MID + mtb*128 + ol)*Cin + icq*32 + icl];
    }
    __syncthreads();
    #pragma unroll
    for (int rep = 0; rep < 2; rep++) {
        int idx = tid + rep*256;               // 0..511
        int ks = idx >> 8, mt = (idx >> 5) & 7, ln = idx & 31;
        int c = ln & 3, rl = ln >> 2;
        int o  = mt*16 + rl;
        int k0 = ks*16 + 2*c, k8 = k0 + 8;
        float vA[4][4], vB[4][4];              // [e][k0,k1,k8,k9] rows o, o+8
        #pragma unroll
        for (int e = 0; e < 4; e++) {
            int ba = (e*128 + o)*33;
            vA[e][0]=ws[ba+k0]; vA[e][1]=ws[ba+k0+1]; vA[e][2]=ws[ba+k8]; vA[e][3]=ws[ba+k8+1];
            int bb = ba + 8*33;
            vB[e][0]=ws[bb+k0]; vB[e][1]=ws[bb+k0+1]; vB[e][2]=ws[bb+k8]; vB[e][3]=ws[bb+k8+1];
        }
        size_t cb = (((size_t)t*4 + icq)*4 + mtb)*2048 + (size_t)idx*4;
        #pragma unroll
        for (int b = 0; b < Bn; b++) {
            float r0 = r[b*4], r1 = r[b*4+1], r2 = r[b*4+2], r3 = r[b*4+3];
            float mA[4], mB[4];
            #pragma unroll
            for (int q = 0; q < 4; q++) {
                mA[q] = r0*vA[0][q] + r1*vA[1][q] + r2*vA[2][q] + r3*vA[3][q];
                mB[q] = r0*vB[0][q] + r1*vB[1][q] + r2*vB[2][q] + r3*vB[3][q];
            }
            float hA[4], hB[4];
            #pragma unroll
            for (int q = 0; q < 4; q++) { hA[q] = bfr(mA[q]); hB[q] = bfr(mB[q]); }
            uint4 vh, vl;
            vh.x = pk2(hA[0], hA[1]);            vh.y = pk2(hB[0], hB[1]);
            vh.z = pk2(hA[2], hA[3]);            vh.w = pk2(hB[2], hB[3]);
            vl.x = pk2(mA[0]-hA[0], mA[1]-hA[1]); vl.y = pk2(mB[0]-hB[0], mB[1]-hB[1]);
            vl.z = pk2(mA[2]-hA[2], mA[3]-hA[3]); vl.w = pk2(mB[2]-hB[2], mB[3]-hB[3]);
            *(uint4*)&g_afh[(size_t)b*NAPK + cb] = vh;
            *(uint4*)&g_afl[(size_t)b*NAPK + cb] = vl;
        }
    }
}

// ---------------- conv: 3x bf16 m16n8k16 + cp.async pipeline --------------------
#define A_HI      0
#define A_LO      8192
#define A_STG     16384
#define A_ALL     (2*A_STG)                 // 32768
#define B_ISTR    328                       // icp stride in words (==8 mod 32)
#define B_STG     (16*B_ISTR*4)             // 20992 bytes per half
#define B_STG2    (2*B_STG)                 // 41984
#define SMEM_CONV (A_ALL + 2*B_STG2)        // 116736

__global__ void __launch_bounds__(256)
conv_mma() {
    extern __shared__ __align__(16) char smem[];
    uint32_t sb = smem_u32(smem);
    int tid = threadIdx.x, wid = tid >> 5, lane = tid & 31;
    int c = lane & 3, rl = lane >> 2;
    int wm = wid & 1, wn = wid >> 1;
    int mtb = blockIdx.x, nt = blockIdx.y, b = blockIdx.z;

    const uint32_t* Abh = g_afh + (size_t)b*NAPK;
    const uint32_t* Abl = g_afl + (size_t)b*NAPK;

    float acc[4][8][4];
    #pragma unroll
    for (int mi = 0; mi < 4; mi++)
        #pragma unroll
        for (int ni = 0; ni < 8; ni++)
            #pragma unroll
            for (int q = 0; q < 4; q++) acc[mi][ni][q] = 0.f;

    uint32_t bb[8];
    #pragma unroll
    for (int ni = 0; ni < 8; ni++) {
        int p = wn*64 + ni*8 + rl;
        bb[ni] = (uint32_t)((((p >> 5)*40) + (p & 31)) << 2);
    }

    auto issueA = [&](int m, int buf) {
        int j = m/7, dx = m - j*7;
        int t = (j >> 2)*7 + dx, icq = j & 3;
        size_t off = ((size_t)((t*4 + icq)*4 + mtb))*2048 + tid*8;
        uint32_t dst = sb + buf*A_STG + tid*32;
        cp16(dst,              Abh + off);
        cp16(dst + 16,         Abh + off + 4);
        cp16(dst + A_LO,       Abl + off);
        cp16(dst + A_LO + 16,  Abl + off + 4);
    };
    auto issueB = [&](int j, int buf) {
        int dy = j >> 2, icq = j & 3;
        int u = tid & 127;
        int icp = u >> 3, h = u & 7;
        size_t srcw = (((size_t)(b*38 + nt*8 + h + dy))*64 + icq*16 + icp)*40;
        const uint32_t* src = (tid < 128) ? (g_xph + srcw) : (g_xpl + srcw);
        uint32_t dst = sb + A_ALL + buf*B_STG2 + ((tid < 128) ? 0 : B_STG)
                     + (uint32_t)(icp*1312 + h*160);
        #pragma unroll
        for (int q = 0; q < 10; q++) cp16(dst + q*16, src + q*4);
    };

    issueB(0, 0); cpcommit();
    issueA(0, 0); cpcommit();
    bool pb = false;

    int j = 0, dx = 0;
    for (int m = 0; m < 196; m++) {
        if (m == 0)      cpwait<0>();
        else if (pb)     cpwait<1>();
        else             cpwait<0>();
        __syncthreads();
        if (m + 1 < 196) { issueA(m + 1, (m + 1) & 1); cpcommit(); }
        pb = false;
        if (dx == 0 && j < 27) { issueB(j + 1, (j + 1) & 1); cpcommit(); pb = true; }

        uint32_t aSh = sb + (m & 1)*A_STG;
        uint32_t aSl = aSh + A_LO;
        uint32_t bSh = sb + A_ALL + (j & 1)*B_STG2 + (uint32_t)(dx << 2);
        uint32_t bSl = bSh + B_STG;
        #pragma unroll
        for (int ks = 0; ks < 2; ks++) {
            uint32_t r0 = (uint32_t)(((ks*8 + c    )*B_ISTR) << 2);
            uint32_t r1 = (uint32_t)(((ks*8 + c + 4)*B_ISTR) << 2);
            uint32_t bh[8][2], bl[8][2];
            #pragma unroll
            for (int ni = 0; ni < 8; ni++) {
                LDS32(bh[ni][0], bSh + r0 + bb[ni]);
                LDS32(bh[ni][1], bSh + r1 + bb[ni]);
                LDS32(bl[ni][0], bSl + r0 + bb[ni]);
                LDS32(bl[ni][1], bSl + r1 + bb[ni]);
            }
            uint32_t af[4][4];
            uint32_t aoff = (uint32_t)((((ks*8 + wm*4)*32) + lane) << 4);
            #pragma unroll
            for (int mi = 0; mi < 4; mi++)
                LDS128(af[mi][0], af[mi][1], af[mi][2], af[mi][3],
                       aSh + aoff + (uint32_t)(mi*512));
            #pragma unroll
            for (int mi = 0; mi < 4; mi++)
                #pragma unroll
                for (int ni = 0; ni < 8; ni++)
                    MMA_BF16(acc[mi][ni], af[mi], bh[ni]);
            #pragma unroll
            for (int mi = 0; mi < 4; mi++)
                #pragma unroll
                for (int ni = 0; ni < 8; ni++)
                    MMA_BF16(acc[mi][ni], af[mi], bl[ni]);
            #pragma unroll
            for (int mi = 0; mi < 4; mi++)
                LDS128(af[mi][0], af[mi][1], af[mi][2], af[mi][3],
                       aSl + aoff + (uint32_t)(mi*512));
            #pragma unroll
            for (int mi = 0; mi < 4; mi++)
                #pragma unroll
                for (int ni = 0; ni < 8; ni++)
                    MMA_BF16(acc[mi][ni], af[mi], bh[ni]);
        }
        if (++dx == 7) { dx = 0; j++; }
    }

    int o0 = mtb*128 + wm*64;
    int p0 = nt*256 + wn*64;
    #pragma unroll
    for (int mi = 0; mi < 4; mi++) {
        int o = o0 + mi*16 + rl;
        float s0 = 0.f, s1 = 0.f;
        float* y0 = g_y + ((size_t)b*MID + o)*HW;
        float* y1 = g_y + ((size_t)b*MID + o + 8)*HW;
        #pragma unroll
        for (int ni = 0; ni < 8; ni++) {
            int p = p0 + ni*8 + 2*c;
            float2 v0 = make_float2(acc[mi][ni][0], acc[mi][ni][1]);
            float2 v1 = make_float2(acc[mi][ni][2], acc[mi][ni][3]);
            *(float2*)(y0 + p) = v0;
            *(float2*)(y1 + p) = v1;
            s0 += v0.x + v0.y;
            s1 += v1.x + v1.y;
        }
        s0 += __shfl_xor_sync(0xffffffffu, s0, 1);
        s0 += __shfl_xor_sync(0xffffffffu, s0, 2);
        s1 += __shfl_xor_sync(0xffffffffu, s1, 1);
        s1 += __shfl_xor_sync(0xffffffffu, s1, 2);
        if (c == 0) {
            atomicAdd(&g_ymean[b*MID + o], s0);
            atomicAdd(&g_ymean[b*MID + o + 8], s1);
        }
    }
}

__global__ void ca_kernel(const float* __restrict__ fc1w, const float* __restrict__ fc1b,
                          const float* __restrict__ fc2w, const float* __restrict__ fc2b) {
    int b = blockIdx.x, t = threadIdx.x;
    __shared__ float m[MID];
    __shared__ float h[32];
    m[t] = g_ymean[b*MID + t] * (1.0f/HW);
    __syncthreads();
    if (t < 32) {
        float s = fc1b[t];
        for (int c = 0; c < MID; c++) s += fc1w[t*MID + c] * m[c];
        h[t] = fmaxf(s, 0.f);
    }
    __syncthreads();
    float s = fc2b[t];
    #pragma unroll
    for (int j = 0; j < 32; j++) s += fc2w[t*32 + j] * h[j];
    g_ca[b*MID + t] = 1.f/(1.f + expf(-s));
}

__global__ void mf_kernel(const float* __restrict__ mask,
                          const float* __restrict__ mpw,
                          const float* __restrict__ mpb) {
    __shared__ float w[Cin];
    int t = threadIdx.x;
    if (t < Cin) w[t] = mpw[t];
    __syncthreads();
    int b = blockIdx.y;
    int p = blockIdx.x*256 + t;
    const float* mb = mask + (size_t)b*Cin*HW + p;
    float s = mpb[0];
    #pragma unroll 8
    for (int c = 0; c < Cin; c++) s += mb[c*HW] * w[c];
    g_mf[b*HW + p] = s;
}

__global__ void __launch_bounds__(128)
final_kernel(const float* __restrict__ predw, float* __restrict__ out) {
    int b = blockIdx.x, pt = blockIdx.y;
    int t = threadIdx.x;
    int p = pt*128 + t;

    __shared__ float pw[64][112];
    float4 acc[28];
    #pragma unroll
    for (int j = 0; j < 28; j++) acc[j] = make_float4(0.f,0.f,0.f,0.f);

    for (int c0 = 0; c0 < MID; c0 += 64) {
        __syncthreads();
        for (int i = t; i < 64*112; i += 128) {
            int cl = i / 112, o = i % 112;
            float v = 0.f;
            if (o < OUTC) v = predw[o*MID + c0 + cl] * g_ca[b*MID + c0 + cl];
            pw[cl][o] = v;
        }
        __syncthreads();
        const float* yb = g_y + ((size_t)b*MID + c0)*HW + p;
        #pragma unroll 4
        for (int cl = 0; cl < 64; cl++) {
            float yv = yb[(size_t)cl*HW];
            const float4* pw4 = (const float4*)pw[cl];
            #pragma unroll
            for (int j = 0; j < 28; j++) {
                float4 w4 = pw4[j];
                acc[j].x += w4.x*yv; acc[j].y += w4.y*yv;
                acc[j].z += w4.z*yv; acc[j].w += w4.w*yv;
            }
        }
    }

    float mf = g_mf[b*HW + p];
    float* dbase = out + BOUT + ((size_t)b*OUTC)*HW + p;
    float* cnt   = out + b*OUTC;
    int lane = t & 31;

#define EMIT(OO, AV) do {                                              \
        if ((OO) < OUTC) {                                             \
            float dv = 1.f/(1.f + expf(-(AV)*mf));                     \
            dbase[(size_t)(OO)*HW] = dv;                               \
            float s_ = dv;                                             \
            s_ += __shfl_down_sync(0xffffffffu, s_, 16);               \
            s_ += __shfl_down_sync(0xffffffffu, s_, 8);                \
            s_ += __shfl_down_sync(0xffffffffu, s_, 4);                \
            s_ += __shfl_down_sync(0xffffffffu, s_, 2);                \
            s_ += __shfl_down_sync(0xffffffffu, s_, 1);                \
            if (lane == 0) atomicAdd(&cnt[(OO)], s_);                  \
        }                                                              \
    } while (0)

    #pragma unroll
    for (int j = 0; j < 28; j++) {
        float4 a = acc[j];
        EMIT(4*j+0, a.x); EMIT(4*j+1, a.y);
        EMIT(4*j+2, a.z); EMIT(4*j+3, a.w);
    }
#undef EMIT
}

extern "C" void kernel_launch(void* const* d_in, const int* in_sizes, int n_in,
                              void* d_out, int out_size) {
    const float* x        = (const float*)d_in[0];
    const float* mask     = (const float*)d_in[1];
    const float* w3       = (const float*)d_in[2];
    const float* w5       = (const float*)d_in[3];
    const float* w7       = (const float*)d_in[4];
    const float* router_w = (const float*)d_in[5];
    const float* router_b = (const float*)d_in[6];
    const float* fc1_w    = (const float*)d_in[7];
    const float* fc1_b    = (const float*)d_in[8];
    const float* fc2_w    = (const float*)d_in[9];
    const float* fc2_b    = (const float*)d_in[10];
    const float* mpw      = (const float*)d_in[11];
    const float* mpb      = (const float*)d_in[12];
    const float* pred_w   = (const float*)d_in[13];
    float* out = (float*)d_out;

    init_kernel<<<32, 256>>>(out);
    routing_kernel<<<Bn, 256>>>(x, router_w, router_b);
    {
        size_t n = (size_t)Bn*XPW;
        xp_zero<<<(int)((n + 255)/256), 256>>>();
    }
    xp_fill<<<dim3(32, Bn), 128>>>(x);
    merge_kernel<<<dim3(MID, NE), 256>>>(w3, w5, w7);

    cudaFuncSetAttribute(fragmix_kernel, cudaFuncAttributeMaxDynamicSharedMemorySize, FM_SMEM);
    fragmix_kernel<<<dim3(49, 16), 256, FM_SMEM>>>();

    cudaFuncSetAttribute(conv_mma, cudaFuncAttributeMaxDynamicSharedMemorySize, SMEM_CONV);
    conv_mma<<<dim3(4, 4, Bn), 256, SMEM_CONV>>>();

    mf_kernel<<<dim3(4, Bn), 256>>>(mask, mpw, mpb);
    ca_kernel<<<Bn, 512>>>(fc1_w, fc1_b, fc2_w, fc2_b);
    final_kernel<<<dim3(Bn, 8), 128>>>(pred_w, out);
}